// round 3
// baseline (speedup 1.0000x reference)
#include <cuda_runtime.h>
#include <math.h>

constexpr int B_ = 64, N_ = 512, C_ = 16, D_ = 64, T_ = 32;
constexpr int VND = B_ * N_ * D_;   // 2,097,152
constexpr int CDD = B_ * C_ * D_;   // 65,536
constexpr int MAXDEG = 160;

__device__ float g_vh0[2][VND];
__device__ float g_vh1[2][VND];
__device__ float g_vc0[2][VND];
__device__ float g_vc1[2][VND];
__device__ float g_ch[2][CDD];
__device__ float g_cc[2][CDD];
__device__ float g_mv[VND];
__device__ float g_vpart[B_ * 8 * 64];   // per-block partial vmsg sums
__device__ float g_mcg[B_ * 256];
__device__ unsigned short g_nbr[(size_t)B_ * N_ * MAXDEG];
__device__ int g_deg[B_ * N_];

__device__ __forceinline__ float sigf(float x) { return 1.0f / (1.0f + expf(-x)); }

// ---------------- adjacency build: one warp per (b,i) row ----------------
__global__ void k_adj(const float* __restrict__ Mvv)
{
    int gw = (blockIdx.x * blockDim.x + threadIdx.x) >> 5;
    int lane = threadIdx.x & 31;
    if (gw >= B_ * N_) return;
    const float* row = Mvv + (size_t)gw * N_;
    unsigned short* outp = g_nbr + (size_t)gw * MAXDEG;
    int cnt = 0;
    for (int base = 0; base < N_; base += 32) {
        float v = row[base + lane];
        unsigned m = __ballot_sync(0xffffffffu, v != 0.0f);
        if (v != 0.0f) {
            int pos = cnt + __popc(m & ((1u << lane) - 1u));
            if (pos < MAXDEG) outp[pos] = (unsigned short)(base + lane);
        }
        cnt += __popc(m);
    }
    if (lane == 0) g_deg[gw] = cnt < MAXDEG ? cnt : MAXDEG;
}

// ---------------- state init (buffer 0) ----------------
__global__ void k_init(const float* __restrict__ vh0i, const float* __restrict__ vh1i,
                       const float* __restrict__ chi)
{
    int i = blockIdx.x * blockDim.x + threadIdx.x;
    if (i < VND) {
        g_vh0[0][i] = vh0i[i];
        g_vh1[0][i] = vh1i[i];
        g_vc0[0][i] = 0.f;
        g_vc1[0][i] = 0.f;
    }
    if (i < CDD) { g_ch[0][i] = chi[i]; g_cc[0][i] = 0.f; }
}

// ---------------- kernel A: mv gather + LSTM1 + vmsg MLP partial sums ----
// grid = 512 (64 batches x 8 tiles of 64 rows), 256 threads
__global__ __launch_bounds__(256, 1)
void k_stepA(int old, const float* __restrict__ Wih1, const float* __restrict__ Whh1,
             const float* __restrict__ bih1, const float* __restrict__ bhh1,
             const float* __restrict__ vW1, const float* __restrict__ vb1,
             const float* __restrict__ vW2, const float* __restrict__ vb2)
{
    extern __shared__ float sm[];
    float* Xs = sm;              // [64][132]
    float* U  = sm + 64 * 132;   // 32768-float scratch
    const int tid = threadIdx.x;
    const int b = blockIdx.x >> 3;
    const int blk = blockIdx.x & 7;
    const int row0 = blk * 64;
    const size_t base = ((size_t)b * N_ + row0) * D_;
    const int nw = 1 - old;

    const float* vh0o = g_vh0[old] + base;
    const float* vh1o = g_vh1[old] + base;

    for (int i = tid; i < 64 * 64; i += 256) {
        int r = i >> 6, d = i & 63;
        Xs[r * 132 + d]      = vh0o[i];
        Xs[r * 132 + 64 + d] = vh1o[i];
    }
    for (int i = tid; i < 64 * 256; i += 256) {
        U[i]         = Wih1[i];
        U[16384 + i] = Whh1[i];
    }
    __syncthreads();

    const int lane = tid & 31, w = tid >> 5;

    // sparse message passing: mv[row] = sum_nbr vh1_old[nbr]
    {
        const float* vh1b = g_vh1[old] + (size_t)b * N_ * D_;
        for (int r = w; r < 64; r += 8) {
            int n = row0 + r;
            int deg = g_deg[b * N_ + n];
            const unsigned short* nb = g_nbr + ((size_t)(b * N_ + n)) * MAXDEG;
            float a0 = 0.f, a1 = 0.f;
            for (int k = 0; k < deg; k++) {
                int j = nb[k];
                float2 v = *(const float2*)(vh1b + (size_t)j * D_ + lane * 2);
                a0 += v.x; a1 += v.y;
            }
            *((float2*)(g_mv + ((size_t)b * N_ + n) * D_) + lane) = make_float2(a0, a1);
        }
    }

    // GEMM: gates1[64][256] = [vh0|vh1][64][128] @ [Wih1;Whh1][128][256]
    float acc[8][8];
    #pragma unroll
    for (int r = 0; r < 8; r++)
        #pragma unroll
        for (int c = 0; c < 8; c++) acc[r][c] = 0.f;
    const float4* W4 = (const float4*)U;
    #pragma unroll 2
    for (int k = 0; k < 128; k++) {
        float xa[8];
        #pragma unroll
        for (int r = 0; r < 8; r++) xa[r] = Xs[(w * 8 + r) * 132 + k];
        float4 w0 = W4[k * 64 + lane * 2];
        float4 w1 = W4[k * 64 + lane * 2 + 1];
        float wb[8] = {w0.x, w0.y, w0.z, w0.w, w1.x, w1.y, w1.z, w1.w};
        #pragma unroll
        for (int r = 0; r < 8; r++)
            #pragma unroll
            for (int c = 0; c < 8; c++)
                acc[r][c] = fmaf(xa[r], wb[c], acc[r][c]);
    }
    __syncthreads();
    float* Gs = U;  // [64][260]
    #pragma unroll
    for (int r = 0; r < 8; r++)
        #pragma unroll
        for (int c = 0; c < 8; c++)
            Gs[(w * 8 + r) * 260 + lane * 8 + c] = acc[r][c];
    __syncthreads();

    // LSTM1 activation
    {
        const float* vc1o = g_vc1[old] + base;
        float* vh1n = g_vh1[nw] + base;
        float* vc1n = g_vc1[nw] + base;
        for (int i = tid; i < 4096; i += 256) {
            int r = i >> 6, d = i & 63;
            float gi = Gs[r * 260 + d]       + bih1[d]       + bhh1[d];
            float gf = Gs[r * 260 + 64 + d]  + bih1[64 + d]  + bhh1[64 + d];
            float gg = Gs[r * 260 + 128 + d] + bih1[128 + d] + bhh1[128 + d];
            float go = Gs[r * 260 + 192 + d] + bih1[192 + d] + bhh1[192 + d];
            float c2 = sigf(gf) * vc1o[i] + sigf(gi) * tanhf(gg);
            vc1n[i] = c2;
            vh1n[i] = sigf(go) * tanhf(c2);
        }
    }
    __syncthreads();

    // vmsg MLP on vh1_old (still staged in Xs), then block-partial row sum
    float* W1s = U;                     // 6400
    float* W2s = U + 6400;              // 6400
    float* Hs  = U + 12800;             // 64*104
    float* Rs  = U + 12800 + 64 * 104;  // 256
    for (int i = tid; i < 6400; i += 256) { W1s[i] = vW1[i]; W2s[i] = vW2[i]; }
    __syncthreads();

    for (int r = w; r < 64; r += 8) {
        float a[4] = {0.f, 0.f, 0.f, 0.f};
        for (int k = 0; k < 64; k++) {
            float x = Xs[r * 132 + 64 + k];
            #pragma unroll
            for (int m = 0; m < 4; m++) {
                int h = lane + 32 * m;
                if (h < 100) a[m] = fmaf(x, W1s[k * 100 + h], a[m]);
            }
        }
        #pragma unroll
        for (int m = 0; m < 4; m++) {
            int h = lane + 32 * m;
            if (h < 100) Hs[r * 104 + h] = fmaxf(a[m] + vb1[h], 0.f);
        }
    }
    __syncthreads();

    {
        int rr = tid >> 2, dg = tid & 3;
        float a2[16];
        #pragma unroll
        for (int i = 0; i < 16; i++) a2[i] = 0.f;
        for (int k = 0; k < 100; k++) {
            float x = Hs[rr * 104 + k];
            #pragma unroll
            for (int i = 0; i < 16; i++)
                a2[i] = fmaf(x, W2s[k * 64 + dg * 16 + i], a2[i]);
        }
        __syncthreads();           // done with W1s region
        float* vsm = W1s;          // reuse as [64][68]
        #pragma unroll
        for (int i = 0; i < 16; i++)
            vsm[rr * 68 + dg * 16 + i] = fmaxf(a2[i] + vb2[dg * 16 + i], 0.f);
        __syncthreads();
        int d = tid & 63, q = tid >> 6;
        float s = 0.f;
        #pragma unroll
        for (int r = 0; r < 16; r++) s += vsm[(q * 16 + r) * 68 + d];
        Rs[q * 64 + d] = s;
        __syncthreads();
        if (tid < 64)
            g_vpart[(b * 8 + blk) * 64 + tid] =
                Rs[tid] + Rs[64 + tid] + Rs[128 + tid] + Rs[192 + tid];
    }
}

// ---------------- kernel C: color-side work; grid = 64, 128 threads ------
__global__ __launch_bounds__(128, 1)
void k_stepC(int old, const int* __restrict__ n_colors,
             const float* __restrict__ cW1, const float* __restrict__ cb1,
             const float* __restrict__ cW2, const float* __restrict__ cb2,
             const float* __restrict__ Wih0, const float* __restrict__ bih0,
             const float* __restrict__ bhh0,
             const float* __restrict__ Wihc, const float* __restrict__ Whhc,
             const float* __restrict__ bihc, const float* __restrict__ bhhc)
{
    extern __shared__ float sm[];
    float* vsum  = sm;                // 64
    float* chs   = vsum + 64;         // 1024
    float* cW1s  = chs + 1024;        // 6400
    float* cW2s  = cW1s + 6400;       // 6400
    float* hid   = cW2s + 6400;       // 16*104
    float* cmsgs = hid + 1664;        // 1024
    float* mcv   = cmsgs + 1024;      // 64
    float* xps   = mcv + 64;          // 256
    float* Whhcs = xps + 256;         // 16384
    float* gcs   = Whhcs + 16384;     // 16*260

    const int tid = threadIdx.x;
    const int b = blockIdx.x;
    const int nw = 1 - old;
    const int nc = n_colors[b];

    if (tid < 64) {
        float s = 0.f;
        #pragma unroll
        for (int blk = 0; blk < 8; blk++) s += g_vpart[(b * 8 + blk) * 64 + tid];
        vsum[tid] = s;
    }
    for (int i = tid; i < 1024; i += 128) chs[i] = g_ch[old][b * 1024 + i];
    for (int i = tid; i < 6400; i += 128) { cW1s[i] = cW1[i]; cW2s[i] = cW2[i]; }
    for (int i = tid; i < 16384; i += 128) Whhcs[i] = Whhc[i];
    __syncthreads();

    for (int idx = tid; idx < 16 * 100; idx += 128) {
        int c = idx / 100, h = idx % 100;
        float a = cb1[h];
        #pragma unroll 4
        for (int d = 0; d < 64; d++) a = fmaf(chs[c * 64 + d], cW1s[d * 100 + h], a);
        hid[c * 104 + h] = fmaxf(a, 0.f);
    }
    __syncthreads();
    for (int idx = tid; idx < 1024; idx += 128) {
        int c = idx >> 6, d = idx & 63;
        float a = cb2[d];
        #pragma unroll 4
        for (int h = 0; h < 100; h++) a = fmaf(hid[c * 104 + h], cW2s[h * 64 + d], a);
        cmsgs[idx] = fmaxf(a, 0.f);
    }
    __syncthreads();
    if (tid < 64) {
        float s = 0.f;
        for (int c = 0; c < nc; c++) s += cmsgs[c * 64 + tid];
        mcv[tid] = s;
    }
    __syncthreads();
    for (int g = tid; g < 256; g += 128) {
        float a = bih0[g] + bhh0[g];
        float x = 0.f;
        #pragma unroll 4
        for (int d = 0; d < 64; d++) {
            a = fmaf(mcv[d],  Wih0[d * 256 + g], a);   // top half of Wih0 (mc rows)
            x = fmaf(vsum[d], Wihc[d * 256 + g], x);
        }
        g_mcg[b * 256 + g] = a;
        xps[g] = x;
    }
    __syncthreads();
    {
        int c = tid >> 3, gg = tid & 7;
        float a[32];
        #pragma unroll
        for (int i = 0; i < 32; i++) a[i] = 0.f;
        for (int k = 0; k < 64; k++) {
            float x = chs[c * 64 + k];
            #pragma unroll
            for (int i = 0; i < 32; i++)
                a[i] = fmaf(x, Whhcs[k * 256 + gg * 32 + i], a[i]);
        }
        float mk = (c < nc) ? 1.f : 0.f;
        #pragma unroll
        for (int i = 0; i < 32; i++) {
            int g = gg * 32 + i;
            gcs[c * 260 + g] = a[i] + mk * xps[g] + bihc[g] + bhhc[g];
        }
    }
    __syncthreads();
    {
        const float* cco = g_cc[old] + b * 1024;
        float* chn = g_ch[nw] + b * 1024;
        float* ccn = g_cc[nw] + b * 1024;
        for (int i = tid; i < 1024; i += 128) {
            int c = i >> 6, d = i & 63;
            float gi = gcs[c * 260 + d];
            float gf = gcs[c * 260 + 64 + d];
            float gg2 = gcs[c * 260 + 128 + d];
            float go = gcs[c * 260 + 192 + d];
            float c2 = sigf(gf) * cco[i] + sigf(gi) * tanhf(gg2);
            ccn[i] = c2;
            chn[i] = sigf(go) * tanhf(c2);
        }
    }
}

// ---------------- kernel B: LSTM0; grid = 512, 256 threads ---------------
__global__ __launch_bounds__(256, 1)
void k_stepB(int old, const float* __restrict__ Wih0, const float* __restrict__ Whh0)
{
    extern __shared__ float sm[];
    float* Xs = sm;
    float* U  = sm + 64 * 132;
    const int tid = threadIdx.x;
    const int b = blockIdx.x >> 3;
    const int row0 = (blockIdx.x & 7) * 64;
    const size_t base = ((size_t)b * N_ + row0) * D_;
    const int nw = 1 - old;

    const float* mvp  = g_mv + base;
    const float* vh0o = g_vh0[old] + base;

    for (int i = tid; i < 64 * 64; i += 256) {
        int r = i >> 6, d = i & 63;
        Xs[r * 132 + d]      = mvp[i];
        Xs[r * 132 + 64 + d] = vh0o[i];
    }
    for (int i = tid; i < 64 * 256; i += 256) {
        U[i]         = Wih0[64 * 256 + i];  // bottom half of Wih0 (mv rows)
        U[16384 + i] = Whh0[i];
    }
    __syncthreads();

    const int lane = tid & 31, w = tid >> 5;
    float acc[8][8];
    #pragma unroll
    for (int r = 0; r < 8; r++)
        #pragma unroll
        for (int c = 0; c < 8; c++) acc[r][c] = 0.f;
    const float4* W4 = (const float4*)U;
    #pragma unroll 2
    for (int k = 0; k < 128; k++) {
        float xa[8];
        #pragma unroll
        for (int r = 0; r < 8; r++) xa[r] = Xs[(w * 8 + r) * 132 + k];
        float4 w0 = W4[k * 64 + lane * 2];
        float4 w1 = W4[k * 64 + lane * 2 + 1];
        float wb[8] = {w0.x, w0.y, w0.z, w0.w, w1.x, w1.y, w1.z, w1.w};
        #pragma unroll
        for (int r = 0; r < 8; r++)
            #pragma unroll
            for (int c = 0; c < 8; c++)
                acc[r][c] = fmaf(xa[r], wb[c], acc[r][c]);
    }
    __syncthreads();
    float* Gs = U;
    #pragma unroll
    for (int r = 0; r < 8; r++)
        #pragma unroll
        for (int c = 0; c < 8; c++)
            Gs[(w * 8 + r) * 260 + lane * 8 + c] = acc[r][c];
    __syncthreads();

    {
        const float* vc0o = g_vc0[old] + base;
        float* vh0n = g_vh0[nw] + base;
        float* vc0n = g_vc0[nw] + base;
        const float* mcg = g_mcg + b * 256;
        for (int i = tid; i < 4096; i += 256) {
            int r = i >> 6, d = i & 63;
            float gi = Gs[r * 260 + d]       + mcg[d];
            float gf = Gs[r * 260 + 64 + d]  + mcg[64 + d];
            float gg = Gs[r * 260 + 128 + d] + mcg[128 + d];
            float go = Gs[r * 260 + 192 + d] + mcg[192 + d];
            float c2 = sigf(gf) * vc0o[i] + sigf(gi) * tanhf(gg);
            vc0n[i] = c2;
            vh0n[i] = sigf(go) * tanhf(c2);
        }
    }
}

// ---------------- vote head: grid = 64, 256 threads ----------------------
__global__ void k_vote(const float* __restrict__ W1, const float* __restrict__ b1,
                       const float* __restrict__ W2, const float* __restrict__ b2,
                       float* __restrict__ out)
{
    __shared__ float w1s[64 * 16];
    __shared__ float w2s[16];
    __shared__ float red[256];
    const int tid = threadIdx.x, b = blockIdx.x;
    for (int i = tid; i < 64 * 16; i += 256) w1s[i] = W1[i];
    if (tid < 16) w2s[tid] = W2[tid];
    __syncthreads();

    float acc = 0.f;
    for (int r = tid; r < N_; r += 256) {
        const float* x = g_vh1[0] + ((size_t)b * N_ + r) * D_;
        float h[16];
        #pragma unroll
        for (int j = 0; j < 16; j++) h[j] = b1[j];
        for (int k = 0; k < 64; k++) {
            float xv = x[k];
            #pragma unroll
            for (int j = 0; j < 16; j++) h[j] = fmaf(xv, w1s[k * 16 + j], h[j]);
        }
        float v = b2[0];
        #pragma unroll
        for (int j = 0; j < 16; j++) v += sigf(h[j]) * w2s[j];
        acc += sigf(v);
    }
    red[tid] = acc;
    __syncthreads();
    for (int s = 128; s > 0; s >>= 1) {
        if (tid < s) red[tid] += red[tid + s];
        __syncthreads();
    }
    if (tid == 0) out[b] = sigf(red[0] / (float)N_);
}

// ---------------- launch -------------------------------------------------
extern "C" void kernel_launch(void* const* d_in, const int* in_sizes, int n_in,
                              void* d_out, int out_size)
{
    const float* Mvv      = (const float*)d_in[0];
    const int*   n_colors = (const int*)d_in[1];
    const float* vh0i     = (const float*)d_in[2];
    const float* vh1i     = (const float*)d_in[3];
    const float* chi      = (const float*)d_in[4];
    const float* Wih0 = (const float*)d_in[5];
    const float* Whh0 = (const float*)d_in[6];
    const float* bih0 = (const float*)d_in[7];
    const float* bhh0 = (const float*)d_in[8];
    const float* Wih1 = (const float*)d_in[9];
    const float* Whh1 = (const float*)d_in[10];
    const float* bih1 = (const float*)d_in[11];
    const float* bhh1 = (const float*)d_in[12];
    const float* Wihc = (const float*)d_in[13];
    const float* Whhc = (const float*)d_in[14];
    const float* bihc = (const float*)d_in[15];
    const float* bhhc = (const float*)d_in[16];
    const float* cW1 = (const float*)d_in[17];
    const float* cb1 = (const float*)d_in[18];
    const float* cW2 = (const float*)d_in[19];
    const float* cb2 = (const float*)d_in[20];
    const float* vW1 = (const float*)d_in[21];
    const float* vb1 = (const float*)d_in[22];
    const float* vW2 = (const float*)d_in[23];
    const float* vb2 = (const float*)d_in[24];
    const float* voteW1 = (const float*)d_in[25];
    const float* voteb1 = (const float*)d_in[26];
    const float* voteW2 = (const float*)d_in[27];
    const float* voteb2 = (const float*)d_in[28];
    float* out = (float*)d_out;

    const int SMEM_AB = (64 * 132 + 32768) * 4;   // 164,864 B
    const int SMEM_C  = 37440 * 4;                 // 149,760 B
    cudaFuncSetAttribute(k_stepA, cudaFuncAttributeMaxDynamicSharedMemorySize, SMEM_AB);
    cudaFuncSetAttribute(k_stepB, cudaFuncAttributeMaxDynamicSharedMemorySize, SMEM_AB);
    cudaFuncSetAttribute(k_stepC, cudaFuncAttributeMaxDynamicSharedMemorySize, SMEM_C);

    k_adj<<<(B_ * N_ * 32 + 255) / 256, 256>>>(Mvv);
    k_init<<<(VND + 255) / 256, 256>>>(vh0i, vh1i, chi);

    for (int t = 0; t < T_; t++) {
        int old = t & 1;
        k_stepA<<<512, 256, SMEM_AB>>>(old, Wih1, Whh1, bih1, bhh1, vW1, vb1, vW2, vb2);
        k_stepC<<<64, 128, SMEM_C>>>(old, n_colors, cW1, cb1, cW2, cb2,
                                     Wih0, bih0, bhh0, Wihc, Whhc, bihc, bhhc);
        k_stepB<<<512, 256, SMEM_AB>>>(old, Wih0, Whh0);
    }
    k_vote<<<B_, 256>>>(voteW1, voteb1, voteW2, voteb2, out);
}

// round 4
// speedup vs baseline: 1.5016x; 1.5016x over previous
#include <cuda_runtime.h>
#include <math.h>

constexpr int B_ = 64, N_ = 512, C_ = 16, D_ = 64, T_ = 32;
constexpr int VND = B_ * N_ * D_;
constexpr int CDD = B_ * C_ * D_;
constexpr int MAXDEG = 160;

__device__ float g_vh0[2][VND];
__device__ float g_vh1[2][VND];
__device__ float g_vc0[2][VND];
__device__ float g_vc1[2][VND];
__device__ float g_ch[2][CDD];
__device__ float g_cc[2][CDD];
__device__ float g_mv[VND];
__device__ float g_vpart[B_ * 8 * 64];
__device__ float g_mcg[B_ * 256];
__device__ unsigned short g_nbr[(size_t)B_ * N_ * MAXDEG];
__device__ int g_deg[B_ * N_];

__device__ __forceinline__ float sigf(float x)  { return 1.0f / (1.0f + __expf(-x)); }
__device__ __forceinline__ float tanhfast(float x) { return 2.0f / (1.0f + __expf(-2.0f * x)) - 1.0f; }

// ---------------- adjacency build: one warp per (b,i) row ----------------
__global__ void k_adj(const float* __restrict__ Mvv)
{
    int gw = (blockIdx.x * blockDim.x + threadIdx.x) >> 5;
    int lane = threadIdx.x & 31;
    if (gw >= B_ * N_) return;
    const float* row = Mvv + (size_t)gw * N_;
    unsigned short* outp = g_nbr + (size_t)gw * MAXDEG;
    int cnt = 0;
    for (int base = 0; base < N_; base += 32) {
        float v = row[base + lane];
        unsigned m = __ballot_sync(0xffffffffu, v != 0.0f);
        if (v != 0.0f) {
            int pos = cnt + __popc(m & ((1u << lane) - 1u));
            if (pos < MAXDEG) outp[pos] = (unsigned short)(base + lane);
        }
        cnt += __popc(m);
    }
    if (lane == 0) g_deg[gw] = cnt < MAXDEG ? cnt : MAXDEG;
}

__global__ void k_init(const float* __restrict__ vh0i, const float* __restrict__ vh1i,
                       const float* __restrict__ chi)
{
    int i = blockIdx.x * blockDim.x + threadIdx.x;
    if (i < VND) {
        g_vh0[0][i] = vh0i[i];
        g_vh1[0][i] = vh1i[i];
        g_vc0[0][i] = 0.f;
        g_vc1[0][i] = 0.f;
    }
    if (i < CDD) { g_ch[0][i] = chi[i]; g_cc[0][i] = 0.f; }
}

// ---------------- kernel A: mv gather + LSTM1 + vmsg MLP ----------------
// grid = 512, 256 threads, 2 blocks/SM. dyn smem = (8448 + 19712)*4 = 112,640 B
__global__ __launch_bounds__(256, 2)
void k_stepA(int old, const float* __restrict__ Wih1, const float* __restrict__ Whh1,
             const float* __restrict__ bih1, const float* __restrict__ bhh1,
             const float* __restrict__ vW1, const float* __restrict__ vb1,
             const float* __restrict__ vW2, const float* __restrict__ vb2)
{
    extern __shared__ float sm[];
    float* Xs = sm;              // [64][132]
    float* U  = sm + 8448;       // 19712-float scratch
    __shared__ float bsum[256];
    const int tid = threadIdx.x;
    const int b = blockIdx.x >> 3;
    const int blk = blockIdx.x & 7;
    const int row0 = blk * 64;
    const size_t base = ((size_t)b * N_ + row0) * D_;
    const int nw = 1 - old;
    const int lane = tid & 31, w = tid >> 5;

    // stage X = [vh0|vh1] with float4; biases
    {
        const float4* v0 = (const float4*)(g_vh0[old] + base);
        const float4* v1 = (const float4*)(g_vh1[old] + base);
        for (int i = tid; i < 1024; i += 256) {
            int r = i >> 4, d4 = i & 15;
            *(float4*)(Xs + r * 132 + d4 * 4)      = v0[i];
            *(float4*)(Xs + r * 132 + 64 + d4 * 4) = v1[i];
        }
        bsum[tid] = bih1[tid] + bhh1[tid];
    }

    // sparse message passing (independent of smem staging)
    {
        const float* vh1b = g_vh1[old] + (size_t)b * N_ * D_;
        for (int r = w; r < 64; r += 8) {
            int n = row0 + r;
            int deg = g_deg[b * N_ + n];
            const unsigned short* nb = g_nbr + ((size_t)(b * N_ + n)) * MAXDEG;
            float a0 = 0.f, a1 = 0.f;
            for (int k = 0; k < deg; k++) {
                int j = nb[k];
                float2 v = *(const float2*)(vh1b + (size_t)j * D_ + lane * 2);
                a0 += v.x; a1 += v.y;
            }
            *((float2*)(g_mv + ((size_t)b * N_ + n) * D_) + lane) = make_float2(a0, a1);
        }
    }

    // GEMM in two K-chunks of 64 (chunk0: Wih1, chunk1: Whh1)
    float acc[8][8];
    #pragma unroll
    for (int r = 0; r < 8; r++)
        #pragma unroll
        for (int c = 0; c < 8; c++) acc[r][c] = 0.f;

    const float* Wsrc[2] = { Wih1, Whh1 };
    for (int chunk = 0; chunk < 2; chunk++) {
        __syncthreads();
        const float4* Wp = (const float4*)Wsrc[chunk];
        float4* U4 = (float4*)U;
        for (int i = tid; i < 4096; i += 256) U4[i] = Wp[i];
        __syncthreads();
        const int koff = chunk * 64;
        #pragma unroll 2
        for (int k = 0; k < 64; k++) {
            float xa[8];
            #pragma unroll
            for (int r = 0; r < 8; r++) xa[r] = Xs[(w * 8 + r) * 132 + koff + k];
            float4 w0 = ((const float4*)U)[k * 64 + lane * 2];
            float4 w1 = ((const float4*)U)[k * 64 + lane * 2 + 1];
            float wb[8] = {w0.x, w0.y, w0.z, w0.w, w1.x, w1.y, w1.z, w1.w};
            #pragma unroll
            for (int r = 0; r < 8; r++)
                #pragma unroll
                for (int c = 0; c < 8; c++)
                    acc[r][c] = fmaf(xa[r], wb[c], acc[r][c]);
        }
    }
    __syncthreads();
    float* Gs = U;  // [64][260]
    #pragma unroll
    for (int r = 0; r < 8; r++)
        #pragma unroll
        for (int c = 0; c < 8; c++)
            Gs[(w * 8 + r) * 260 + lane * 8 + c] = acc[r][c];
    __syncthreads();

    // LSTM1 activation
    {
        const float* vc1o = g_vc1[old] + base;
        float* vh1n = g_vh1[nw] + base;
        float* vc1n = g_vc1[nw] + base;
        for (int i = tid; i < 4096; i += 256) {
            int r = i >> 6, d = i & 63;
            float gi = Gs[r * 260 + d]       + bsum[d];
            float gf = Gs[r * 260 + 64 + d]  + bsum[64 + d];
            float gg = Gs[r * 260 + 128 + d] + bsum[128 + d];
            float go = Gs[r * 260 + 192 + d] + bsum[192 + d];
            float c2 = sigf(gf) * vc1o[i] + sigf(gi) * tanhfast(gg);
            vc1n[i] = c2;
            vh1n[i] = sigf(go) * tanhfast(c2);
        }
    }
    __syncthreads();

    // vmsg MLP on vh1_old (in Xs cols 64..127), then block-partial row sum
    float* W1s = U;            // 6400
    float* W2s = U + 6400;     // 6400
    float* Hs  = U + 12800;    // 64*104 = 6656
    float* Rs  = U + 19456;    // 256
    {
        const float4* p1 = (const float4*)vW1;
        const float4* p2 = (const float4*)vW2;
        for (int i = tid; i < 1600; i += 256) {
            ((float4*)W1s)[i] = p1[i];
            ((float4*)W2s)[i] = p2[i];
        }
    }
    __syncthreads();

    for (int r = w; r < 64; r += 8) {
        float a0[4] = {0.f,0.f,0.f,0.f}, a1[4] = {0.f,0.f,0.f,0.f};
        for (int k = 0; k < 64; k += 2) {
            float x0 = Xs[r * 132 + 64 + k];
            float x1 = Xs[r * 132 + 64 + k + 1];
            #pragma unroll
            for (int m = 0; m < 4; m++) {
                int h = lane + 32 * m;
                if (h < 100) {
                    a0[m] = fmaf(x0, W1s[k * 100 + h], a0[m]);
                    a1[m] = fmaf(x1, W1s[(k + 1) * 100 + h], a1[m]);
                }
            }
        }
        #pragma unroll
        for (int m = 0; m < 4; m++) {
            int h = lane + 32 * m;
            if (h < 100) Hs[r * 104 + h] = fmaxf(a0[m] + a1[m] + vb1[h], 0.f);
        }
    }
    __syncthreads();

    {
        int rr = tid >> 2, dg = tid & 3;
        float a2[16];
        #pragma unroll
        for (int i = 0; i < 16; i++) a2[i] = 0.f;
        for (int k = 0; k < 100; k++) {
            float x = Hs[rr * 104 + k];
            #pragma unroll
            for (int i = 0; i < 16; i++)
                a2[i] = fmaf(x, W2s[k * 64 + dg * 16 + i], a2[i]);
        }
        __syncthreads();
        float* vsm = W1s;  // reuse as [64][68]
        #pragma unroll
        for (int i = 0; i < 16; i++)
            vsm[rr * 68 + dg * 16 + i] = fmaxf(a2[i] + vb2[dg * 16 + i], 0.f);
        __syncthreads();
        int d = tid & 63, q = tid >> 6;
        float s = 0.f;
        #pragma unroll
        for (int r = 0; r < 16; r++) s += vsm[(q * 16 + r) * 68 + d];
        Rs[q * 64 + d] = s;
        __syncthreads();
        if (tid < 64)
            g_vpart[(b * 8 + blk) * 64 + tid] =
                Rs[tid] + Rs[64 + tid] + Rs[128 + tid] + Rs[192 + tid];
    }
}

// ---------------- kernel C: color-side; grid = 64, 256 threads -----------
__global__ __launch_bounds__(256, 1)
void k_stepC(int old, const int* __restrict__ n_colors,
             const float* __restrict__ cW1, const float* __restrict__ cb1,
             const float* __restrict__ cW2, const float* __restrict__ cb2,
             const float* __restrict__ Wih0, const float* __restrict__ bih0,
             const float* __restrict__ bhh0,
             const float* __restrict__ Wihc, const float* __restrict__ Whhc,
             const float* __restrict__ bihc, const float* __restrict__ bhhc)
{
    extern __shared__ float sm[];
    float* vsum  = sm;                // 64
    float* chs   = vsum + 64;         // 1024
    float* cW1s  = chs + 1024;        // 6400
    float* cW2s  = cW1s + 6400;       // 6400
    float* hid   = cW2s + 6400;       // 1664
    float* cmsgs = hid + 1664;        // 1024
    float* mcv   = cmsgs + 1024;      // 64
    float* xps   = mcv + 64;          // 256
    float* Whhcs = xps + 256;         // 16384
    float* gcs   = Whhcs + 16384;     // 4160

    const int tid = threadIdx.x;
    const int b = blockIdx.x;
    const int nw = 1 - old;
    const int nc = n_colors[b];

    if (tid < 64) {
        float s = 0.f;
        #pragma unroll
        for (int blk = 0; blk < 8; blk++) s += g_vpart[(b * 8 + blk) * 64 + tid];
        vsum[tid] = s;
    }
    {
        const float4* pc = (const float4*)(g_ch[old] + b * 1024);
        for (int i = tid; i < 256; i += 256) ((float4*)chs)[i] = pc[i];
        const float4* p1 = (const float4*)cW1;
        const float4* p2 = (const float4*)cW2;
        for (int i = tid; i < 1600; i += 256) {
            ((float4*)cW1s)[i] = p1[i];
            ((float4*)cW2s)[i] = p2[i];
        }
        const float4* pw = (const float4*)Whhc;
        for (int i = tid; i < 4096; i += 256) ((float4*)Whhcs)[i] = pw[i];
    }
    __syncthreads();

    // hid = relu(ch @ cW1 + cb1): 1600 outputs, 2-way split accumulators
    for (int idx = tid; idx < 16 * 100; idx += 256) {
        int c = idx / 100, h = idx % 100;
        float a0 = 0.f, a1 = 0.f;
        #pragma unroll 8
        for (int d = 0; d < 64; d += 2) {
            a0 = fmaf(chs[c * 64 + d],     cW1s[d * 100 + h],       a0);
            a1 = fmaf(chs[c * 64 + d + 1], cW1s[(d + 1) * 100 + h], a1);
        }
        hid[c * 104 + h] = fmaxf(a0 + a1 + cb1[h], 0.f);
    }
    __syncthreads();
    // cmsg = relu(hid @ cW2 + cb2): 1024 outputs
    for (int idx = tid; idx < 1024; idx += 256) {
        int c = idx >> 6, d = idx & 63;
        float a0 = 0.f, a1 = 0.f;
        #pragma unroll 10
        for (int h = 0; h < 100; h += 2) {
            a0 = fmaf(hid[c * 104 + h],     cW2s[h * 64 + d],       a0);
            a1 = fmaf(hid[c * 104 + h + 1], cW2s[(h + 1) * 64 + d], a1);
        }
        cmsgs[idx] = fmaxf(a0 + a1 + cb2[d], 0.f);
    }
    __syncthreads();
    if (tid < 64) {
        float s = 0.f;
        for (int c = 0; c < nc; c++) s += cmsgs[c * 64 + tid];
        mcv[tid] = s;
    }
    __syncthreads();
    // mcg = mc @ Wih0_top + biases ; xps = vsum @ Wihc  (one output/thread)
    {
        int g = tid;
        float a0 = bih0[g] + bhh0[g], a1 = 0.f;
        float x0 = 0.f, x1 = 0.f;
        #pragma unroll 8
        for (int d = 0; d < 64; d += 2) {
            a0 = fmaf(mcv[d],      Wih0[d * 256 + g],       a0);
            a1 = fmaf(mcv[d + 1],  Wih0[(d + 1) * 256 + g], a1);
            x0 = fmaf(vsum[d],     Wihc[d * 256 + g],       x0);
            x1 = fmaf(vsum[d + 1], Wihc[(d + 1) * 256 + g], x1);
        }
        g_mcg[b * 256 + g] = a0 + a1;
        xps[g] = x0 + x1;
    }
    __syncthreads();
    // gates_c = mask*xps + ch_old @ Whhc + biases : thread -> (c, 16 gates)
    {
        int c = tid >> 4, seg = (tid & 15) * 16;
        float a[16];
        #pragma unroll
        for (int i = 0; i < 16; i++) a[i] = 0.f;
        for (int k = 0; k < 64; k++) {
            float x = chs[c * 64 + k];
            #pragma unroll
            for (int i = 0; i < 16; i++)
                a[i] = fmaf(x, Whhcs[k * 256 + seg + i], a[i]);
        }
        float mk = (c < nc) ? 1.f : 0.f;
        #pragma unroll
        for (int i = 0; i < 16; i++) {
            int g = seg + i;
            gcs[c * 260 + g] = a[i] + mk * xps[g] + bihc[g] + bhhc[g];
        }
    }
    __syncthreads();
    {
        const float* cco = g_cc[old] + b * 1024;
        float* chn = g_ch[nw] + b * 1024;
        float* ccn = g_cc[nw] + b * 1024;
        for (int i = tid; i < 1024; i += 256) {
            int c = i >> 6, d = i & 63;
            float gi  = gcs[c * 260 + d];
            float gf  = gcs[c * 260 + 64 + d];
            float gg2 = gcs[c * 260 + 128 + d];
            float go  = gcs[c * 260 + 192 + d];
            float c2 = sigf(gf) * cco[i] + sigf(gi) * tanhfast(gg2);
            ccn[i] = c2;
            chn[i] = sigf(go) * tanhfast(c2);
        }
    }
}

// ---------------- kernel B: LSTM0; grid = 512, 256 threads, 2 blk/SM -----
// dyn smem = (8448 + 16640)*4 = 100,352 B
__global__ __launch_bounds__(256, 2)
void k_stepB(int old, const float* __restrict__ Wih0, const float* __restrict__ Whh0)
{
    extern __shared__ float sm[];
    float* Xs = sm;
    float* U  = sm + 8448;
    __shared__ float mcgs[256];
    const int tid = threadIdx.x;
    const int b = blockIdx.x >> 3;
    const int row0 = (blockIdx.x & 7) * 64;
    const size_t base = ((size_t)b * N_ + row0) * D_;
    const int nw = 1 - old;
    const int lane = tid & 31, w = tid >> 5;

    {
        const float4* mv4 = (const float4*)(g_mv + base);
        const float4* v0  = (const float4*)(g_vh0[old] + base);
        for (int i = tid; i < 1024; i += 256) {
            int r = i >> 4, d4 = i & 15;
            *(float4*)(Xs + r * 132 + d4 * 4)      = mv4[i];
            *(float4*)(Xs + r * 132 + 64 + d4 * 4) = v0[i];
        }
        mcgs[tid] = g_mcg[b * 256 + tid];
    }

    float acc[8][8];
    #pragma unroll
    for (int r = 0; r < 8; r++)
        #pragma unroll
        for (int c = 0; c < 8; c++) acc[r][c] = 0.f;

    const float* Wsrc[2] = { Wih0 + 64 * 256, Whh0 };
    for (int chunk = 0; chunk < 2; chunk++) {
        __syncthreads();
        const float4* Wp = (const float4*)Wsrc[chunk];
        float4* U4 = (float4*)U;
        for (int i = tid; i < 4096; i += 256) U4[i] = Wp[i];
        __syncthreads();
        const int koff = chunk * 64;
        #pragma unroll 2
        for (int k = 0; k < 64; k++) {
            float xa[8];
            #pragma unroll
            for (int r = 0; r < 8; r++) xa[r] = Xs[(w * 8 + r) * 132 + koff + k];
            float4 w0 = ((const float4*)U)[k * 64 + lane * 2];
            float4 w1 = ((const float4*)U)[k * 64 + lane * 2 + 1];
            float wb[8] = {w0.x, w0.y, w0.z, w0.w, w1.x, w1.y, w1.z, w1.w};
            #pragma unroll
            for (int r = 0; r < 8; r++)
                #pragma unroll
                for (int c = 0; c < 8; c++)
                    acc[r][c] = fmaf(xa[r], wb[c], acc[r][c]);
        }
    }
    __syncthreads();
    float* Gs = U;
    #pragma unroll
    for (int r = 0; r < 8; r++)
        #pragma unroll
        for (int c = 0; c < 8; c++)
            Gs[(w * 8 + r) * 260 + lane * 8 + c] = acc[r][c];
    __syncthreads();

    {
        const float* vc0o = g_vc0[old] + base;
        float* vh0n = g_vh0[nw] + base;
        float* vc0n = g_vc0[nw] + base;
        for (int i = tid; i < 4096; i += 256) {
            int r = i >> 6, d = i & 63;
            float gi = Gs[r * 260 + d]       + mcgs[d];
            float gf = Gs[r * 260 + 64 + d]  + mcgs[64 + d];
            float gg = Gs[r * 260 + 128 + d] + mcgs[128 + d];
            float go = Gs[r * 260 + 192 + d] + mcgs[192 + d];
            float c2 = sigf(gf) * vc0o[i] + sigf(gi) * tanhfast(gg);
            vc0n[i] = c2;
            vh0n[i] = sigf(go) * tanhfast(c2);
        }
    }
}

// ---------------- vote head ----------------------------------------------
__global__ void k_vote(const float* __restrict__ W1, const float* __restrict__ b1,
                       const float* __restrict__ W2, const float* __restrict__ b2,
                       float* __restrict__ out)
{
    __shared__ float w1s[64 * 16];
    __shared__ float w2s[16];
    __shared__ float red[256];
    const int tid = threadIdx.x, b = blockIdx.x;
    for (int i = tid; i < 64 * 16; i += 256) w1s[i] = W1[i];
    if (tid < 16) w2s[tid] = W2[tid];
    __syncthreads();

    float acc = 0.f;
    for (int r = tid; r < N_; r += 256) {
        const float* x = g_vh1[0] + ((size_t)b * N_ + r) * D_;
        float h[16];
        #pragma unroll
        for (int j = 0; j < 16; j++) h[j] = b1[j];
        for (int k = 0; k < 64; k++) {
            float xv = x[k];
            #pragma unroll
            for (int j = 0; j < 16; j++) h[j] = fmaf(xv, w1s[k * 16 + j], h[j]);
        }
        float v = b2[0];
        #pragma unroll
        for (int j = 0; j < 16; j++) v += sigf(h[j]) * w2s[j];
        acc += sigf(v);
    }
    red[tid] = acc;
    __syncthreads();
    for (int s = 128; s > 0; s >>= 1) {
        if (tid < s) red[tid] += red[tid + s];
        __syncthreads();
    }
    if (tid == 0) out[b] = sigf(red[0] / (float)N_);
}

// ---------------- launch -------------------------------------------------
extern "C" void kernel_launch(void* const* d_in, const int* in_sizes, int n_in,
                              void* d_out, int out_size)
{
    const float* Mvv      = (const float*)d_in[0];
    const int*   n_colors = (const int*)d_in[1];
    const float* vh0i     = (const float*)d_in[2];
    const float* vh1i     = (const float*)d_in[3];
    const float* chi      = (const float*)d_in[4];
    const float* Wih0 = (const float*)d_in[5];
    const float* Whh0 = (const float*)d_in[6];
    const float* bih0 = (const float*)d_in[7];
    const float* bhh0 = (const float*)d_in[8];
    const float* Wih1 = (const float*)d_in[9];
    const float* Whh1 = (const float*)d_in[10];
    const float* bih1 = (const float*)d_in[11];
    const float* bhh1 = (const float*)d_in[12];
    const float* Wihc = (const float*)d_in[13];
    const float* Whhc = (const float*)d_in[14];
    const float* bihc = (const float*)d_in[15];
    const float* bhhc = (const float*)d_in[16];
    const float* cW1 = (const float*)d_in[17];
    const float* cb1 = (const float*)d_in[18];
    const float* cW2 = (const float*)d_in[19];
    const float* cb2 = (const float*)d_in[20];
    const float* vW1 = (const float*)d_in[21];
    const float* vb1 = (const float*)d_in[22];
    const float* vW2 = (const float*)d_in[23];
    const float* vb2 = (const float*)d_in[24];
    const float* voteW1 = (const float*)d_in[25];
    const float* voteb1 = (const float*)d_in[26];
    const float* voteW2 = (const float*)d_in[27];
    const float* voteb2 = (const float*)d_in[28];
    float* out = (float*)d_out;

    const int SMEM_A = (8448 + 19712) * 4;   // 112,640 B
    const int SMEM_B = (8448 + 16640) * 4;   // 100,352 B
    const int SMEM_C = 37440 * 4;            // 149,760 B
    cudaFuncSetAttribute(k_stepA, cudaFuncAttributeMaxDynamicSharedMemorySize, SMEM_A);
    cudaFuncSetAttribute(k_stepB, cudaFuncAttributeMaxDynamicSharedMemorySize, SMEM_B);
    cudaFuncSetAttribute(k_stepC, cudaFuncAttributeMaxDynamicSharedMemorySize, SMEM_C);

    k_adj<<<(B_ * N_ * 32 + 255) / 256, 256>>>(Mvv);
    k_init<<<(VND + 255) / 256, 256>>>(vh0i, vh1i, chi);

    for (int t = 0; t < T_; t++) {
        int old = t & 1;
        k_stepA<<<512, 256, SMEM_A>>>(old, Wih1, Whh1, bih1, bhh1, vW1, vb1, vW2, vb2);
        k_stepC<<<64, 256, SMEM_C>>>(old, n_colors, cW1, cb1, cW2, cb2,
                                     Wih0, bih0, bhh0, Wihc, Whhc, bihc, bhhc);
        k_stepB<<<512, 256, SMEM_B>>>(old, Wih0, Whh0);
    }
    k_vote<<<B_, 256>>>(voteW1, voteb1, voteW2, voteb2, out);
}